// round 15
// baseline (speedup 1.0000x reference)
#include <cuda_runtime.h>
#include <cuda_fp16.h>
#include <cstdint>

#define DD   512
#define LL   128
#define HALF 4096
#define MROWS 8192

// Scratch
__device__ uint32_t g_Ah [MROWS * 256];      // f16 [nobs; cur], half2-packed
__device__ uint32_t g_Wth[2 * 1024 * 256];   // f16 W, TRANSPOSED [job][n][k], half2
__device__ uint32_t g_Pu[MROWS * 512];       // half2 projections: cols 0..255 wq, 256..511 uh
__device__ float    g_ZS[MROWS * 1024];      // cols 0..511 Z (tf32), 512..1023 S (f32)

__device__ __forceinline__ uint32_t f2tf32(float x) {
    uint32_t r; asm("cvt.rna.tf32.f32 %0, %1;" : "=r"(r) : "f"(x)); return r;
}
__device__ __forceinline__ void mma_tf32(float* d, const uint32_t* a, const uint32_t* b) {
    asm volatile(
        "mma.sync.aligned.m16n8k8.row.col.f32.tf32.tf32.f32 "
        "{%0,%1,%2,%3}, {%4,%5,%6,%7}, {%8,%9}, {%0,%1,%2,%3};"
        : "+f"(d[0]), "+f"(d[1]), "+f"(d[2]), "+f"(d[3])
        : "r"(a[0]), "r"(a[1]), "r"(a[2]), "r"(a[3]), "r"(b[0]), "r"(b[1]));
}
__device__ __forceinline__ void mma_f16(float* d, const uint32_t* a, const uint32_t* b) {
    asm volatile(
        "mma.sync.aligned.m16n8k16.row.col.f32.f16.f16.f32 "
        "{%0,%1,%2,%3}, {%4,%5,%6,%7}, {%8,%9}, {%0,%1,%2,%3};"
        : "+f"(d[0]), "+f"(d[1]), "+f"(d[2]), "+f"(d[3])
        : "r"(a[0]), "r"(a[1]), "r"(a[2]), "r"(a[3]), "r"(b[0]), "r"(b[1]));
}
__device__ __forceinline__ void ldsm4(uint32_t* r, uint32_t addr) {
    asm volatile("ldmatrix.sync.aligned.m8n8.x4.shared.b16 {%0,%1,%2,%3}, [%4];"
        : "=r"(r[0]), "=r"(r[1]), "=r"(r[2]), "=r"(r[3]) : "r"(addr));
}
__device__ __forceinline__ uint32_t hadd2u(uint32_t a, uint32_t b) {
    uint32_t r; asm("add.rn.f16x2 %0,%1,%2;" : "=r"(r) : "r"(a), "r"(b)); return r;
}
__device__ __forceinline__ uint32_t tanh2u(uint32_t a) {
    uint32_t r; asm("tanh.approx.f16x2 %0,%1;" : "=r"(r) : "r"(a)); return r;
}
__device__ __forceinline__ uint32_t hfma2u(uint32_t a, uint32_t b, uint32_t c) {
    uint32_t r; asm("fma.rn.f16x2 %0,%1,%2,%3;" : "=r"(r) : "r"(a), "r"(b), "r"(c)); return r;
}
__device__ __forceinline__ float h2sum(uint32_t u) {
    __half2 h = *reinterpret_cast<__half2*>(&u);
    float2 f = __half22float2(h);
    return f.x + f.y;
}
__device__ __forceinline__ void cp16(uint32_t dst, const void* src) {
    asm volatile("cp.async.cg.shared.global [%0], [%1], 16;" :: "r"(dst), "l"(src));
}

// ---------------------------------------------------------------------------
// Prep: bid<4096 round A to f16; 4096..5119 transpose+round W panels
// ---------------------------------------------------------------------------
__global__ __launch_bounds__(256) void prep_k(
    const float* __restrict__ cur, const float* __restrict__ nobs,
    const float* __restrict__ Wq, const float* __restrict__ Wc,
    const float* __restrict__ Wout)
{
    __shared__ float ts[32][33];
    const int bid = blockIdx.x, tid = threadIdx.x;
    if (bid < 4096) {
        int i = bid * 256 + tid;
        int idx4 = i * 4;
        int row = idx4 >> 9, col = idx4 & 511;
        const float* src = ((row < HALF) ? nobs + (size_t)row * 512
                                         : cur + (size_t)(row - HALF) * 512) + col;
        float4 x = *(const float4*)src;
        __half2 h0 = __floats2half2_rn(x.x, x.y);
        __half2 h1 = __floats2half2_rn(x.z, x.w);
        uint2 o;
        o.x = *reinterpret_cast<uint32_t*>(&h0);
        o.y = *reinterpret_cast<uint32_t*>(&h1);
        *(uint2*)&g_Ah[(size_t)row * 256 + (col >> 1)] = o;
        return;
    }
    const int wb = bid - 4096;
    const int job = wb >> 9;
    const int rem = wb & 511;
    const int kt = rem >> 5, nt = rem & 31;
    const int tx = tid & 31, ty = tid >> 5;
    #pragma unroll
    for (int i = 0; i < 4; i++) {
        int k = kt * 32 + ty + i * 8;
        int n = nt * 32 + tx;
        float x;
        if (job == 0) x = (n < 512) ? Wq[(size_t)k * 512 + n] : Wc[(size_t)k * 512 + n - 512];
        else          x = (n < 512) ? Wout[(size_t)k * 512 + n]
                                    : Wout[(size_t)(512 + k) * 512 + n - 512];
        ts[ty + i * 8][tx] = x;
    }
    __syncthreads();
    __half* Wh = (__half*)g_Wth;
    #pragma unroll
    for (int i = 0; i < 4; i++) {
        int n = nt * 32 + ty + i * 8;
        int k = kt * 32 + tx;
        Wh[((size_t)job * 1024 + n) * 512 + k] = __float2half_rn(ts[tx][ty + i * 8]);
    }
}

// ---------------------------------------------------------------------------
// f16 GEMM (m16n8k16) — R10 champion, unchanged. CTA 128x128, 4-stage.
// ---------------------------------------------------------------------------
#define GSTRIDE (128*20 + 128*20)        // 5120 u32 per stage
#define GSMEM   (4 * GSTRIDE * 4)        // 81920 B

__global__ void __launch_bounds__(256, 2) gemm_k(const float* __restrict__ bq)
{
    extern __shared__ uint32_t sm[];
    const uint32_t sbase = (uint32_t)__cvta_generic_to_shared(sm);
    const int job = blockIdx.z;
    const int m0 = blockIdx.y * 128, n0 = blockIdx.x * 128;
    const int tid = threadIdx.x, warp = tid >> 5, lane = tid & 31;
    const int wm = (warp >> 1) * 32, wn = (warp & 1) * 64;

    const uint32_t* Bg = g_Wth + (size_t)job * 1024 * 256;

    const int s_r = tid >> 1;
    const int s_c = (tid & 1) * 8;
    auto issue = [&](int kt) {
        const uint32_t base = sbase + (kt & 3) * (GSTRIDE * 4);
        #pragma unroll
        for (int h = 0; h < 2; h++) {
            int c = s_c + h * 4;
            cp16(base + (s_r * 20 + c) * 4,
                 g_Ah + (size_t)(m0 + s_r) * 256 + kt * 16 + c);
            cp16(base + (128 * 20 + s_r * 20 + c) * 4,
                 Bg + (size_t)(n0 + s_r) * 256 + kt * 16 + c);
        }
        asm volatile("cp.async.commit_group;");
    };

    const int q = lane >> 3, lr = lane & 7;
    uint32_t aoff[2], boff[4];
    #pragma unroll
    for (int mf = 0; mf < 2; mf++)
        aoff[mf] = (wm + mf * 16 + (q & 1) * 8 + lr) * 80 + (q >> 1) * 16;
    #pragma unroll
    for (int p = 0; p < 4; p++)
        boff[p] = 128 * 80 + (wn + p * 16 + (q >> 1) * 8 + lr) * 80 + (q & 1) * 16;

    float acc[2][8][4];
    #pragma unroll
    for (int i = 0; i < 2; i++)
        #pragma unroll
        for (int j = 0; j < 8; j++)
            #pragma unroll
            for (int k = 0; k < 4; k++) acc[i][j][k] = 0.f;

    issue(0); issue(1); issue(2);

    for (int kt = 0; kt < 16; kt++) {
        if (kt < 14)       asm volatile("cp.async.wait_group 2;");
        else if (kt == 14) asm volatile("cp.async.wait_group 1;");
        else               asm volatile("cp.async.wait_group 0;");
        __syncthreads();
        if (kt < 13) issue(kt + 3);

        const uint32_t base = sbase + (kt & 3) * (GSTRIDE * 4);
        #pragma unroll
        for (int ks = 0; ks < 2; ks++) {
            const uint32_t kkb = ks * 32;
            uint32_t af[2][4], bf[4][4];
            ldsm4(af[0], base + aoff[0] + kkb);
            ldsm4(af[1], base + aoff[1] + kkb);
            #pragma unroll
            for (int p = 0; p < 4; p++) ldsm4(bf[p], base + boff[p] + kkb);
            #pragma unroll
            for (int p = 0; p < 4; p++) {
                mma_f16(acc[0][2 * p],     af[0], &bf[p][0]);
                mma_f16(acc[0][2 * p + 1], af[0], &bf[p][2]);
                mma_f16(acc[1][2 * p],     af[1], &bf[p][0]);
                mma_f16(acc[1][2 * p + 1], af[1], &bf[p][2]);
            }
        }
    }

    #pragma unroll
    for (int mf = 0; mf < 2; mf++) {
        #pragma unroll
        for (int nf = 0; nf < 8; nf++) {
            int row = m0 + wm + mf * 16 + (lane >> 2);
            int col = n0 + wn + nf * 8 + (lane & 3) * 2;
            if (job == 0) {
                float b0 = 0.f, b1 = 0.f;
                if (col < 512) { b0 = bq[col]; b1 = bq[col + 1]; }
                __half2 h0 = __floats2half2_rn(acc[mf][nf][0] + b0, acc[mf][nf][1] + b1);
                __half2 h1 = __floats2half2_rn(acc[mf][nf][2] + b0, acc[mf][nf][3] + b1);
                g_Pu[(size_t)row * 512 + (col >> 1)]       = *reinterpret_cast<uint32_t*>(&h0);
                g_Pu[(size_t)(row + 8) * 512 + (col >> 1)] = *reinterpret_cast<uint32_t*>(&h1);
            } else {
                float2 v0, v1;
                if (col < 512) {
                    v0 = make_float2(__uint_as_float(f2tf32(acc[mf][nf][0])),
                                     __uint_as_float(f2tf32(acc[mf][nf][1])));
                    v1 = make_float2(__uint_as_float(f2tf32(acc[mf][nf][2])),
                                     __uint_as_float(f2tf32(acc[mf][nf][3])));
                } else {
                    v0 = make_float2(acc[mf][nf][0], acc[mf][nf][1]);
                    v1 = make_float2(acc[mf][nf][2], acc[mf][nf][3]);
                }
                *(float2*)&g_ZS[(size_t)row * 1024 + col]       = v0;
                *(float2*)&g_ZS[(size_t)(row + 8) * 1024 + col] = v1;
            }
        }
    }
}

// ---------------------------------------------------------------------------
// Fused scores + softmax + BOTH-CALL align@Z + mix + S + bias -> out.
// CTA = (b, 16-row t-chunk), handles call 0 and call 1. 256 CTAs, 2 CTAs/SM.
// smem u32 (20992 = 83968 B, same as R10):
//   phase A: wq2[2][16][256]@0 | uh2[32][260]@8192 | v2s[256]@16512
//   sc[2][16][132]f @16768
//   phase B: Zs0[16][516]f@0 | Zs1[16][516]f@8256 (alias wq2/uh2/v2s)
// ---------------------------------------------------------------------------
#define SC_SMEM (20992 * 4)

__global__ void __launch_bounds__(256, 2) score_ctx_kernel(
    const float* __restrict__ v, const float* __restrict__ mix,
    const float* __restrict__ bout, float* __restrict__ out)
{
    extern __shared__ uint32_t smu[];
    const uint32_t sb = (uint32_t)__cvta_generic_to_shared(smu);
    uint32_t* wq2 = smu;                    // [2][16][256]
    uint32_t* uh2 = smu + 8192;             // [32][260]
    uint32_t* v2s = smu + 16512;            // [256]
    float*    sc  = (float*)(smu + 16768);  // [2][16][132]
    float*    Zs0 = (float*)smu;            // [16][516]
    float*    Zs1 = (float*)smu + 8256;     // [16][516]

    const int bid = blockIdx.x;             // 256 CTAs
    const int b   = bid >> 3;
    const int t0  = (bid & 7) * 16;
    const int tid = threadIdx.x, warp = tid >> 5, lane = tid & 31;
    const float m = __ldg(mix);

    {
        float2 vv = *(const float2*)(v + 2 * tid);
        __half2 h = __floats2half2_rn(vv.x, vv.y);
        v2s[tid] = *reinterpret_cast<uint32_t*>(&h);
    }
    // stage wq for both calls: 2 x 16 x 64 uint4
    #pragma unroll
    for (int call = 0; call < 2; call++) {
        #pragma unroll
        for (int it = 0; it < 4; it++) {
            int idx = tid + it * 256;
            int r = idx >> 6, c4 = (idx & 63) * 4;
            *(uint4*)&wq2[call * 4096 + r * 256 + c4] =
                *(const uint4*)&g_Pu[(size_t)(call * HALF + b * LL + t0 + r) * 512 + c4];
        }
    }

    const int tw = warp * 2;
    float s_r[2][2][4];

    // -------- phase A: both calls --------
    #pragma unroll
    for (int call = 0; call < 2; call++) {
        const int membase = (1 - call) * HALF + b * LL;
        for (int st = 0; st < 4; st++) {
            __syncthreads();
            #pragma unroll
            for (int it = 0; it < 8; it++) {
                int idx = tid + it * 256;
                int r = idx >> 6, c4 = (idx & 63) * 4;
                *(uint4*)&uh2[r * 260 + c4] =
                    *(const uint4*)&g_Pu[(size_t)(membase + st * 32 + r) * 512 + 256 + c4];
            }
            __syncthreads();

            float a0 = 0.f, a1 = 0.f;
            const uint32_t* up  = &uh2[lane * 260];
            const uint32_t* w0p = &wq2[call * 4096 + tw * 256];
            const uint32_t* w1p = w0p + 256;
            #pragma unroll 4
            for (int j = 0; j < 64; j += 2) {
                uint4 uA = *(const uint4*)(up + j * 4);
                uint4 uB = *(const uint4*)(up + j * 4 + 4);
                uint4 vA = *(const uint4*)(v2s + j * 4);
                uint4 vB = *(const uint4*)(v2s + j * 4 + 4);
                uint4 wA, wB; uint32_t c2;

                wA = *(const uint4*)(w0p + j * 4);
                wB = *(const uint4*)(w0p + j * 4 + 4);
                c2 = 0;
                c2 = hfma2u(vA.x, tanh2u(hadd2u(wA.x, uA.x)), c2);
                c2 = hfma2u(vA.y, tanh2u(hadd2u(wA.y, uA.y)), c2);
                c2 = hfma2u(vA.z, tanh2u(hadd2u(wA.z, uA.z)), c2);
                c2 = hfma2u(vA.w, tanh2u(hadd2u(wA.w, uA.w)), c2);
                c2 = hfma2u(vB.x, tanh2u(hadd2u(wB.x, uB.x)), c2);
                c2 = hfma2u(vB.y, tanh2u(hadd2u(wB.y, uB.y)), c2);
                c2 = hfma2u(vB.z, tanh2u(hadd2u(wB.z, uB.z)), c2);
                c2 = hfma2u(vB.w, tanh2u(hadd2u(wB.w, uB.w)), c2);
                a0 += h2sum(c2);

                wA = *(const uint4*)(w1p + j * 4);
                wB = *(const uint4*)(w1p + j * 4 + 4);
                c2 = 0;
                c2 = hfma2u(vA.x, tanh2u(hadd2u(wA.x, uA.x)), c2);
                c2 = hfma2u(vA.y, tanh2u(hadd2u(wA.y, uA.y)), c2);
                c2 = hfma2u(vA.z, tanh2u(hadd2u(wA.z, uA.z)), c2);
                c2 = hfma2u(vA.w, tanh2u(hadd2u(wA.w, uA.w)), c2);
                c2 = hfma2u(vB.x, tanh2u(hadd2u(wB.x, uB.x)), c2);
                c2 = hfma2u(vB.y, tanh2u(hadd2u(wB.y, uB.y)), c2);
                c2 = hfma2u(vB.z, tanh2u(hadd2u(wB.z, uB.z)), c2);
                c2 = hfma2u(vB.w, tanh2u(hadd2u(wB.w, uB.w)), c2);
                a1 += h2sum(c2);
            }
            s_r[call][0][st] = a0; s_r[call][1][st] = a1;
        }
    }

    // -------- softmax per (call, t-row); fold mix weight into align --------
    #pragma unroll
    for (int call = 0; call < 2; call++) {
        const float w = call ? m : (1.f - m);
        #pragma unroll
        for (int ti = 0; ti < 2; ti++) {
            float mx = fmaxf(fmaxf(s_r[call][ti][0], s_r[call][ti][1]),
                             fmaxf(s_r[call][ti][2], s_r[call][ti][3]));
            #pragma unroll
            for (int o = 16; o > 0; o >>= 1)
                mx = fmaxf(mx, __shfl_xor_sync(0xffffffffu, mx, o));
            float e[4], sum = 0.f;
            #pragma unroll
            for (int j = 0; j < 4; j++) { e[j] = __expf(s_r[call][ti][j] - mx); sum += e[j]; }
            #pragma unroll
            for (int o = 16; o > 0; o >>= 1)
                sum += __shfl_xor_sync(0xffffffffu, sum, o);
            float sw = w / sum;
            #pragma unroll
            for (int j = 0; j < 4; j++)
                sc[call * 2112 + (tw + ti) * 132 + j * 32 + lane] =
                    __uint_as_float(f2tf32(e[j] * sw));
        }
    }

    // -------- phase B: accB = sum over both calls of align' @ Z --------
    float accB[8][4];
    #pragma unroll
    for (int nf = 0; nf < 8; nf++)
        #pragma unroll
        for (int k = 0; k < 4; k++) accB[nf][k] = 0.f;

    const int ncol = warp * 64;
    const int mrow = lane >> 2;

    auto stageZ = [&](int step, int buf) {
        const int call = step >> 3, kc = step & 7;
        const int membase = (1 - call) * HALF + b * LL;
        const uint32_t dstb = sb + (uint32_t)buf * (8256 * 4);
        #pragma unroll
        for (int it = 0; it < 8; it++) {
            int idx = tid + it * 256;
            int r = idx >> 7, c4 = (idx & 127) * 4;
            cp16(dstb + (r * 516 + c4) * 4,
                 &g_ZS[(size_t)(membase + kc * 16 + r) * 1024 + c4]);
        }
        asm volatile("cp.async.commit_group;");
    };

    __syncthreads();               // phase A + softmax stores done; alias region free
    stageZ(0, 0);

    for (int step = 0; step < 16; step++) {
        if (step) __syncthreads();
        if (step < 15) stageZ(step + 1, (step + 1) & 1);
        if (step < 15) asm volatile("cp.async.wait_group 1;");
        else           asm volatile("cp.async.wait_group 0;");
        __syncthreads();

        const int call = step >> 3, kc = step & 7;
        const float* Zc = (step & 1) ? Zs1 : Zs0;
        const float* scb = sc + call * 2112;
        #pragma unroll
        for (int kf = 0; kf < 2; kf++) {
            const int scol = (kc * 2 + kf) * 8 + (lane & 3);
            uint32_t af[4];
            af[0] = __float_as_uint(scb[mrow * 132 + scol]);
            af[1] = __float_as_uint(scb[(mrow + 8) * 132 + scol]);
            af[2] = __float_as_uint(scb[mrow * 132 + scol + 4]);
            af[3] = __float_as_uint(scb[(mrow + 8) * 132 + scol + 4]);
            const int rk = kf * 8 + (lane & 3);
            #pragma unroll
            for (int nf = 0; nf < 8; nf++) {
                const int c = ncol + nf * 8 + mrow;
                uint32_t bf[2];
                bf[0] = __float_as_uint(Zc[rk * 516 + c]);
                bf[1] = __float_as_uint(Zc[(rk + 4) * 516 + c]);
                mma_tf32(accB[nf], af, bf);
            }
        }
    }

    // -------- epilogue: + w0*S0 + m*S1 + bout -> out --------
    const float w0 = 1.f - m;
    const size_t rbase = (size_t)b * LL + t0;
    #pragma unroll
    for (int nf = 0; nf < 8; nf++) {
        int col = ncol + nf * 8 + (lane & 3) * 2;
        float2 bo = *(const float2*)(bout + col);
        #pragma unroll
        for (int h = 0; h < 2; h++) {
            size_t row = rbase + mrow + h * 8;
            float2 s0 = *(const float2*)&g_ZS[row * 1024 + 512 + col];
            float2 s1 = *(const float2*)&g_ZS[(HALF + row) * 1024 + 512 + col];
            float2 o;
            o.x = accB[nf][2 * h]     + w0 * s0.x + m * s1.x + bo.x;
            o.y = accB[nf][2 * h + 1] + w0 * s0.y + m * s1.y + bo.y;
            *(float2*)&out[row * 512 + col] = o;
        }
    }
}

extern "C" void kernel_launch(void* const* d_in, const int* in_sizes, int n_in,
                              void* d_out, int out_size)
{
    const float* cur  = (const float*)d_in[0];
    const float* nobs = (const float*)d_in[1];
    const float* Wq   = (const float*)d_in[2];
    const float* bq   = (const float*)d_in[3];
    const float* Wc   = (const float*)d_in[4];
    const float* v    = (const float*)d_in[5];
    const float* Wout = (const float*)d_in[6];
    const float* bout = (const float*)d_in[7];
    const float* mix  = (const float*)d_in[8];
    float* out = (float*)d_out;

    cudaFuncSetAttribute(gemm_k, cudaFuncAttributeMaxDynamicSharedMemorySize, GSMEM);
    cudaFuncSetAttribute(score_ctx_kernel, cudaFuncAttributeMaxDynamicSharedMemorySize, SC_SMEM);

    // 0) round inputs to f16, transpose W
    prep_k<<<5120, 256>>>(cur, nobs, Wq, Wc, Wout);
    // 1) Both GEMMs (R10 champion): z=0 -> g_Pu, z=1 -> g_ZS
    gemm_k<<<dim3(8, 64, 2), 256, GSMEM>>>(bq);
    // 2) fused scores + softmax + both-call align@Z + mix + S + bias -> out
    score_ctx_kernel<<<256, 256, SC_SMEM>>>(v, mix, bout, out);
}

// round 16
// speedup vs baseline: 1.0397x; 1.0397x over previous
#include <cuda_runtime.h>
#include <cuda_fp16.h>
#include <cstdint>

#define DD   512
#define LL   128
#define HALF 4096
#define MROWS 8192

// Scratch
__device__ uint32_t g_Ah [MROWS * 256];      // f16 [nobs; cur], half2-packed
__device__ uint32_t g_Wth[2 * 1024 * 256];   // f16 W, TRANSPOSED [job][n][k], half2
__device__ uint32_t g_Pu[MROWS * 512];       // half2 projections: cols 0..255 wq, 256..511 uh
__device__ float    g_ZS[MROWS * 1024];      // cols 0..511 Z (tf32), 512..1023 S (f32)
__device__ float    g_O [2 * HALF * 512];    // align @ Z per call

__device__ __forceinline__ uint32_t f2tf32(float x) {
    uint32_t r; asm("cvt.rna.tf32.f32 %0, %1;" : "=r"(r) : "f"(x)); return r;
}
__device__ __forceinline__ void mma_tf32(float* d, const uint32_t* a, const uint32_t* b) {
    asm volatile(
        "mma.sync.aligned.m16n8k8.row.col.f32.tf32.tf32.f32 "
        "{%0,%1,%2,%3}, {%4,%5,%6,%7}, {%8,%9}, {%0,%1,%2,%3};"
        : "+f"(d[0]), "+f"(d[1]), "+f"(d[2]), "+f"(d[3])
        : "r"(a[0]), "r"(a[1]), "r"(a[2]), "r"(a[3]), "r"(b[0]), "r"(b[1]));
}
__device__ __forceinline__ void mma_f16(float* d, const uint32_t* a, const uint32_t* b) {
    asm volatile(
        "mma.sync.aligned.m16n8k16.row.col.f32.f16.f16.f32 "
        "{%0,%1,%2,%3}, {%4,%5,%6,%7}, {%8,%9}, {%0,%1,%2,%3};"
        : "+f"(d[0]), "+f"(d[1]), "+f"(d[2]), "+f"(d[3])
        : "r"(a[0]), "r"(a[1]), "r"(a[2]), "r"(a[3]), "r"(b[0]), "r"(b[1]));
}
__device__ __forceinline__ void ldsm4(uint32_t* r, uint32_t addr) {
    asm volatile("ldmatrix.sync.aligned.m8n8.x4.shared.b16 {%0,%1,%2,%3}, [%4];"
        : "=r"(r[0]), "=r"(r[1]), "=r"(r[2]), "=r"(r[3]) : "r"(addr));
}
__device__ __forceinline__ uint32_t hadd2u(uint32_t a, uint32_t b) {
    uint32_t r; asm("add.rn.f16x2 %0,%1,%2;" : "=r"(r) : "r"(a), "r"(b)); return r;
}
__device__ __forceinline__ uint32_t tanh2u(uint32_t a) {
    uint32_t r; asm("tanh.approx.f16x2 %0,%1;" : "=r"(r) : "r"(a)); return r;
}
__device__ __forceinline__ uint32_t hfma2u(uint32_t a, uint32_t b, uint32_t c) {
    uint32_t r; asm("fma.rn.f16x2 %0,%1,%2,%3;" : "=r"(r) : "r"(a), "r"(b), "r"(c)); return r;
}
__device__ __forceinline__ float h2sum(uint32_t u) {
    __half2 h = *reinterpret_cast<__half2*>(&u);
    float2 f = __half22float2(h);
    return f.x + f.y;
}
__device__ __forceinline__ void cp16(uint32_t dst, const void* src) {
    asm volatile("cp.async.cg.shared.global [%0], [%1], 16;" :: "r"(dst), "l"(src));
}

// ---------------------------------------------------------------------------
// Prep: bid<2048 round A to f16 (2 float4 items per thread);
//       2048..3071 transpose+round W panels
// ---------------------------------------------------------------------------
__global__ __launch_bounds__(256) void prep_k(
    const float* __restrict__ cur, const float* __restrict__ nobs,
    const float* __restrict__ Wq, const float* __restrict__ Wc,
    const float* __restrict__ Wout)
{
    __shared__ float ts[32][33];
    const int bid = blockIdx.x, tid = threadIdx.x;
    if (bid < 2048) {
        #pragma unroll
        for (int h = 0; h < 2; h++) {
            int i = bid * 256 + tid + h * 524288;
            int idx4 = i * 4;
            int row = idx4 >> 9, col = idx4 & 511;
            const float* src = ((row < HALF) ? nobs + (size_t)row * 512
                                             : cur + (size_t)(row - HALF) * 512) + col;
            float4 x = *(const float4*)src;
            __half2 h0 = __floats2half2_rn(x.x, x.y);
            __half2 h1 = __floats2half2_rn(x.z, x.w);
            uint2 o;
            o.x = *reinterpret_cast<uint32_t*>(&h0);
            o.y = *reinterpret_cast<uint32_t*>(&h1);
            *(uint2*)&g_Ah[(size_t)row * 256 + (col >> 1)] = o;
        }
        return;
    }
    const int wb = bid - 2048;             // < 1024
    const int job = wb >> 9;
    const int rem = wb & 511;
    const int kt = rem >> 5, nt = rem & 31;
    const int tx = tid & 31, ty = tid >> 5;
    #pragma unroll
    for (int i = 0; i < 4; i++) {
        int k = kt * 32 + ty + i * 8;
        int n = nt * 32 + tx;
        float x;
        if (job == 0) x = (n < 512) ? Wq[(size_t)k * 512 + n] : Wc[(size_t)k * 512 + n - 512];
        else          x = (n < 512) ? Wout[(size_t)k * 512 + n]
                                    : Wout[(size_t)(512 + k) * 512 + n - 512];
        ts[ty + i * 8][tx] = x;
    }
    __syncthreads();
    __half* Wh = (__half*)g_Wth;
    #pragma unroll
    for (int i = 0; i < 4; i++) {
        int n = nt * 32 + ty + i * 8;
        int k = kt * 32 + tx;
        Wh[((size_t)job * 1024 + n) * 512 + k] = __float2half_rn(ts[tx][ty + i * 8]);
    }
}

// ---------------------------------------------------------------------------
// f16 GEMM (m16n8k16), LDSM frags, cp.async 4-stage, ONE sync per k-tile.
// (R10 champion, unchanged.) CTA 128x128, 8 warps, warp tile 32x64, BK=32.
// job = blockIdx.z: 0 -> g_Pu (+bq); 1 -> g_ZS.
// ---------------------------------------------------------------------------
#define GSTRIDE (128*20 + 128*20)        // 5120 u32 per stage
#define GSMEM   (4 * GSTRIDE * 4)        // 81920 B

__global__ void __launch_bounds__(256, 2) gemm_k(const float* __restrict__ bq)
{
    extern __shared__ uint32_t sm[];
    const uint32_t sbase = (uint32_t)__cvta_generic_to_shared(sm);
    const int job = blockIdx.z;
    const int m0 = blockIdx.y * 128, n0 = blockIdx.x * 128;
    const int tid = threadIdx.x, warp = tid >> 5, lane = tid & 31;
    const int wm = (warp >> 1) * 32, wn = (warp & 1) * 64;

    const uint32_t* Bg = g_Wth + (size_t)job * 1024 * 256;

    const int s_r = tid >> 1;
    const int s_c = (tid & 1) * 8;
    auto issue = [&](int kt) {
        const uint32_t base = sbase + (kt & 3) * (GSTRIDE * 4);
        #pragma unroll
        for (int h = 0; h < 2; h++) {
            int c = s_c + h * 4;
            cp16(base + (s_r * 20 + c) * 4,
                 g_Ah + (size_t)(m0 + s_r) * 256 + kt * 16 + c);
            cp16(base + (128 * 20 + s_r * 20 + c) * 4,
                 Bg + (size_t)(n0 + s_r) * 256 + kt * 16 + c);
        }
        asm volatile("cp.async.commit_group;");
    };

    const int q = lane >> 3, lr = lane & 7;
    uint32_t aoff[2], boff[4];
    #pragma unroll
    for (int mf = 0; mf < 2; mf++)
        aoff[mf] = (wm + mf * 16 + (q & 1) * 8 + lr) * 80 + (q >> 1) * 16;
    #pragma unroll
    for (int p = 0; p < 4; p++)
        boff[p] = 128 * 80 + (wn + p * 16 + (q >> 1) * 8 + lr) * 80 + (q & 1) * 16;

    float acc[2][8][4];
    #pragma unroll
    for (int i = 0; i < 2; i++)
        #pragma unroll
        for (int j = 0; j < 8; j++)
            #pragma unroll
            for (int k = 0; k < 4; k++) acc[i][j][k] = 0.f;

    issue(0); issue(1); issue(2);

    for (int kt = 0; kt < 16; kt++) {
        if (kt < 14)       asm volatile("cp.async.wait_group 2;");
        else if (kt == 14) asm volatile("cp.async.wait_group 1;");
        else               asm volatile("cp.async.wait_group 0;");
        __syncthreads();
        if (kt < 13) issue(kt + 3);

        const uint32_t base = sbase + (kt & 3) * (GSTRIDE * 4);
        #pragma unroll
        for (int ks = 0; ks < 2; ks++) {
            const uint32_t kkb = ks * 32;
            uint32_t af[2][4], bf[4][4];
            ldsm4(af[0], base + aoff[0] + kkb);
            ldsm4(af[1], base + aoff[1] + kkb);
            #pragma unroll
            for (int p = 0; p < 4; p++) ldsm4(bf[p], base + boff[p] + kkb);
            #pragma unroll
            for (int p = 0; p < 4; p++) {
                mma_f16(acc[0][2 * p],     af[0], &bf[p][0]);
                mma_f16(acc[0][2 * p + 1], af[0], &bf[p][2]);
                mma_f16(acc[1][2 * p],     af[1], &bf[p][0]);
                mma_f16(acc[1][2 * p + 1], af[1], &bf[p][2]);
            }
        }
    }

    #pragma unroll
    for (int mf = 0; mf < 2; mf++) {
        #pragma unroll
        for (int nf = 0; nf < 8; nf++) {
            int row = m0 + wm + mf * 16 + (lane >> 2);
            int col = n0 + wn + nf * 8 + (lane & 3) * 2;
            if (job == 0) {
                float b0 = 0.f, b1 = 0.f;
                if (col < 512) { b0 = bq[col]; b1 = bq[col + 1]; }
                __half2 h0 = __floats2half2_rn(acc[mf][nf][0] + b0, acc[mf][nf][1] + b1);
                __half2 h1 = __floats2half2_rn(acc[mf][nf][2] + b0, acc[mf][nf][3] + b1);
                g_Pu[(size_t)row * 512 + (col >> 1)]       = *reinterpret_cast<uint32_t*>(&h0);
                g_Pu[(size_t)(row + 8) * 512 + (col >> 1)] = *reinterpret_cast<uint32_t*>(&h1);
            } else {
                float2 v0, v1;
                if (col < 512) {
                    v0 = make_float2(__uint_as_float(f2tf32(acc[mf][nf][0])),
                                     __uint_as_float(f2tf32(acc[mf][nf][1])));
                    v1 = make_float2(__uint_as_float(f2tf32(acc[mf][nf][2])),
                                     __uint_as_float(f2tf32(acc[mf][nf][3])));
                } else {
                    v0 = make_float2(acc[mf][nf][0], acc[mf][nf][1]);
                    v1 = make_float2(acc[mf][nf][2], acc[mf][nf][3]);
                }
                *(float2*)&g_ZS[(size_t)row * 1024 + col]       = v0;
                *(float2*)&g_ZS[(size_t)(row + 8) * 1024 + col] = v1;
            }
        }
    }
}

// ---------------------------------------------------------------------------
// Fused scores + softmax + align@Z (R10 champion, unchanged).
// 32 t-rows per CTA, 256 CTAs, 2 CTAs/SM.
// ---------------------------------------------------------------------------
#define SC_WQ   0
#define SC_UH   8192
#define SC_V    (8192 + 8320)
#define SC_SC   (8192 + 8320 + 256)
#define SC_SMEM ((8192 + 8320 + 256 + 32 * 132) * 4)   // 83968 B

__global__ void __launch_bounds__(256, 2) score_ctx_kernel(const float* __restrict__ v)
{
    extern __shared__ uint32_t smu[];
    const uint32_t sb = (uint32_t)__cvta_generic_to_shared(smu);
    uint32_t* wq2 = smu + SC_WQ;            // [32][256]
    uint32_t* uh2 = smu + SC_UH;            // [32][260]
    uint32_t* v2s = smu + SC_V;             // [256]
    float*    sc  = (float*)(smu + SC_SC);  // [32][132]
    float*    Zs0 = (float*)smu;            // phase B: [16][516] buf 0
    float*    Zs1 = (float*)smu + 8256;     //          [16][516] buf 1

    const int bid  = blockIdx.x;            // 256 CTAs
    const int call = bid >> 7;
    const int b    = (bid >> 2) & 31;
    const int t0   = (bid & 3) * 32;
    const int tid  = threadIdx.x, warp = tid >> 5, lane = tid & 31;

    const int srcbase = call * HALF + b * LL + t0;
    const int membase = (1 - call) * HALF + b * LL;

    {
        float2 vv = *(const float2*)(v + 2 * tid);
        __half2 h = __floats2half2_rn(vv.x, vv.y);
        v2s[tid] = *reinterpret_cast<uint32_t*>(&h);
    }
    #pragma unroll
    for (int it = 0; it < 8; it++) {
        int idx = tid + it * 256;
        int r = idx >> 6, c4 = (idx & 63) * 4;
        *(uint4*)&wq2[r * 256 + c4] = *(const uint4*)&g_Pu[(size_t)(srcbase + r) * 512 + c4];
    }

    const int tw = warp * 4;
    float s_r[4][4];

    for (int st = 0; st < 4; st++) {
        __syncthreads();
        #pragma unroll
        for (int it = 0; it < 8; it++) {
            int idx = tid + it * 256;
            int r = idx >> 6, c4 = (idx & 63) * 4;
            *(uint4*)&uh2[r * 260 + c4] =
                *(const uint4*)&g_Pu[(size_t)(membase + st * 32 + r) * 512 + 256 + c4];
        }
        __syncthreads();

        float a0 = 0.f, a1 = 0.f, a2 = 0.f, a3 = 0.f;
        const uint32_t* up  = &uh2[lane * 260];
        const uint32_t* w0p = &wq2[tw * 256];
        const uint32_t* w1p = w0p + 256;
        const uint32_t* w2p = w0p + 512;
        const uint32_t* w3p = w0p + 768;
        #pragma unroll 2
        for (int j = 0; j < 64; j += 2) {
            uint4 uA = *(const uint4*)(up + j * 4);
            uint4 uB = *(const uint4*)(up + j * 4 + 4);
            uint4 vA = *(const uint4*)(v2s + j * 4);
            uint4 vB = *(const uint4*)(v2s + j * 4 + 4);
            uint4 wA, wB; uint32_t c2;

            wA = *(const uint4*)(w0p + j * 4);
            wB = *(const uint4*)(w0p + j * 4 + 4);
            c2 = 0;
            c2 = hfma2u(vA.x, tanh2u(hadd2u(wA.x, uA.x)), c2);
            c2 = hfma2u(vA.y, tanh2u(hadd2u(wA.y, uA.y)), c2);
            c2 = hfma2u(vA.z, tanh2u(hadd2u(wA.z, uA.z)), c2);
            c2 = hfma2u(vA.w, tanh2u(hadd2u(wA.w, uA.w)), c2);
            c2 = hfma2u(vB.x, tanh2u(hadd2u(wB.x, uB.x)), c2);
            c2 = hfma2u(vB.y, tanh2u(hadd2u(wB.y, uB.y)), c2);
            c2 = hfma2u(vB.z, tanh2u(hadd2u(wB.z, uB.z)), c2);
            c2 = hfma2u(vB.w, tanh2u(hadd2u(wB.w, uB.w)), c2);
            a0 += h2sum(c2);

            wA = *(const uint4*)(w1p + j * 4);
            wB = *(const uint4*)(w1p + j * 4 + 4);
            c2 = 0;
            c2 = hfma2u(vA.x, tanh2u(hadd2u(wA.x, uA.x)), c2);
            c2 = hfma2u(vA.y, tanh2u(hadd2u(wA.y, uA.y)), c2);
            c2 = hfma2u(vA.z, tanh2u(hadd2u(wA.z, uA.z)), c2);
            c2 = hfma2u(vA.w, tanh2u(hadd2u(wA.w, uA.w)), c2);
            c2 = hfma2u(vB.x, tanh2u(hadd2u(wB.x, uB.x)), c2);
            c2 = hfma2u(vB.y, tanh2u(hadd2u(wB.y, uB.y)), c2);
            c2 = hfma2u(vB.z, tanh2u(hadd2u(wB.z, uB.z)), c2);
            c2 = hfma2u(vB.w, tanh2u(hadd2u(wB.w, uB.w)), c2);
            a1 += h2sum(c2);

            wA = *(const uint4*)(w2p + j * 4);
            wB = *(const uint4*)(w2p + j * 4 + 4);
            c2 = 0;
            c2 = hfma2u(vA.x, tanh2u(hadd2u(wA.x, uA.x)), c2);
            c2 = hfma2u(vA.y, tanh2u(hadd2u(wA.y, uA.y)), c2);
            c2 = hfma2u(vA.z, tanh2u(hadd2u(wA.z, uA.z)), c2);
            c2 = hfma2u(vA.w, tanh2u(hadd2u(wA.w, uA.w)), c2);
            c2 = hfma2u(vB.x, tanh2u(hadd2u(wB.x, uB.x)), c2);
            c2 = hfma2u(vB.y, tanh2u(hadd2u(wB.y, uB.y)), c2);
            c2 = hfma2u(vB.z, tanh2u(hadd2u(wB.z, uB.z)), c2);
            c2 = hfma2u(vB.w, tanh2u(hadd2u(wB.w, uB.w)), c2);
            a2 += h2sum(c2);

            wA = *(const uint4*)(w3p + j * 4);
            wB = *(const uint4*)(w3p + j * 4 + 4);
            c2 = 0;
            c2 = hfma2u(vA.x, tanh2u(hadd2u(wA.x, uA.x)), c2);
            c2 = hfma2u(vA.y, tanh2u(hadd2u(wA.y, uA.y)), c2);
            c2 = hfma2u(vA.z, tanh2u(hadd2u(wA.z, uA.z)), c2);
            c2 = hfma2u(vA.w, tanh2u(hadd2u(wA.w, uA.w)), c2);
            c2 = hfma2u(vB.x, tanh2u(hadd2u(wB.x, uB.x)), c2);
            c2 = hfma2u(vB.y, tanh2u(hadd2u(wB.y, uB.y)), c2);
            c2 = hfma2u(vB.z, tanh2u(hadd2u(wB.z, uB.z)), c2);
            c2 = hfma2u(vB.w, tanh2u(hadd2u(wB.w, uB.w)), c2);
            a3 += h2sum(c2);
        }
        s_r[0][st] = a0; s_r[1][st] = a1; s_r[2][st] = a2; s_r[3][st] = a3;
    }

    #pragma unroll
    for (int ti = 0; ti < 4; ti++) {
        float mx = fmaxf(fmaxf(s_r[ti][0], s_r[ti][1]), fmaxf(s_r[ti][2], s_r[ti][3]));
        #pragma unroll
        for (int o = 16; o > 0; o >>= 1)
            mx = fmaxf(mx, __shfl_xor_sync(0xffffffffu, mx, o));
        float e[4], sum = 0.f;
        #pragma unroll
        for (int j = 0; j < 4; j++) { e[j] = __expf(s_r[ti][j] - mx); sum += e[j]; }
        #pragma unroll
        for (int o = 16; o > 0; o >>= 1)
            sum += __shfl_xor_sync(0xffffffffu, sum, o);
        float inv = 1.0f / sum;
        #pragma unroll
        for (int j = 0; j < 4; j++)
            sc[(tw + ti) * 132 + j * 32 + lane] = __uint_as_float(f2tf32(e[j] * inv));
    }

    // ---- phase B: out[32][512] = align @ Z via tf32 mma, ping-pong Zs ----
    float accB[2][8][4];
    #pragma unroll
    for (int mf = 0; mf < 2; mf++)
        #pragma unroll
        for (int nf = 0; nf < 8; nf++)
            #pragma unroll
            for (int k = 0; k < 4; k++) accB[mf][nf][k] = 0.f;

    const int ncol = warp * 64;
    const int mrow = lane >> 2;

    auto stageZ = [&](int kc, int buf) {
        const uint32_t dstb = sb + (uint32_t)buf * (8256 * 4);
        #pragma unroll
        for (int it = 0; it < 8; it++) {
            int idx = tid + it * 256;
            int r = idx >> 7, c4 = (idx & 127) * 4;
            cp16(dstb + (r * 516 + c4) * 4,
                 &g_ZS[(size_t)(membase + kc * 16 + r) * 1024 + c4]);
        }
        asm volatile("cp.async.commit_group;");
    };

    __syncthreads();
    stageZ(0, 0);

    for (int kc = 0; kc < 8; kc++) {
        if (kc) __syncthreads();
        if (kc < 7) stageZ(kc + 1, (kc + 1) & 1);
        if (kc < 7) asm volatile("cp.async.wait_group 1;");
        else        asm volatile("cp.async.wait_group 0;");
        __syncthreads();

        const float* Zc = (kc & 1) ? Zs1 : Zs0;
        #pragma unroll
        for (int kf = 0; kf < 2; kf++) {
            const int scol = (kc * 2 + kf) * 8 + (lane & 3);
            uint32_t af[2][4];
            #pragma unroll
            for (int mf = 0; mf < 2; mf++) {
                int mr = mf * 16 + mrow;
                af[mf][0] = __float_as_uint(sc[mr * 132 + scol]);
                af[mf][1] = __float_as_uint(sc[(mr + 8) * 132 + scol]);
                af[mf][2] = __float_as_uint(sc[mr * 132 + scol + 4]);
                af[mf][3] = __float_as_uint(sc[(mr + 8) * 132 + scol + 4]);
            }
            const int rk = kf * 8 + (lane & 3);
            #pragma unroll
            for (int nf = 0; nf < 8; nf++) {
                const int c = ncol + nf * 8 + mrow;
                uint32_t bf[2];
                bf[0] = __float_as_uint(Zc[rk * 516 + c]);
                bf[1] = __float_as_uint(Zc[(rk + 4) * 516 + c]);
                mma_tf32(accB[0][nf], af[0], bf);
                mma_tf32(accB[1][nf], af[1], bf);
            }
        }
    }

    const size_t base = (size_t)call * HALF + (size_t)b * LL + t0;
    #pragma unroll
    for (int mf = 0; mf < 2; mf++) {
        #pragma unroll
        for (int nf = 0; nf < 8; nf++) {
            int c = ncol + nf * 8 + (lane & 3) * 2;
            size_t row = base + mf * 16 + mrow;
            *(float2*)&g_O[row * 512 + c]       = make_float2(accB[mf][nf][0], accB[mf][nf][1]);
            *(float2*)&g_O[(row + 8) * 512 + c] = make_float2(accB[mf][nf][2], accB[mf][nf][3]);
        }
    }
}

// out = (1-m)*(O0 + S_nobs) + m*(O1 + S_cur) + bout   (2 items/thread for MLP)
__global__ __launch_bounds__(256) void combine_kernel(
    const float* __restrict__ mix, const float* __restrict__ bout,
    float* __restrict__ out)
{
    float m = __ldg(mix);
    float w0 = 1.f - m;
    #pragma unroll
    for (int h = 0; h < 2; h++) {
        int i = blockIdx.x * 256 + threadIdx.x + h * 262144;
        int r = i >> 7, c4 = (i & 127) * 4;
        float4 o0 = *(float4*)&g_O[(size_t)r * 512 + c4];
        float4 o1 = *(float4*)&g_O[(size_t)(HALF + r) * 512 + c4];
        float4 s0 = *(const float4*)&g_ZS[(size_t)r * 1024 + 512 + c4];
        float4 s1 = *(const float4*)&g_ZS[(size_t)(HALF + r) * 1024 + 512 + c4];
        float4 bo = *(const float4*)(bout + c4);
        float4 o;
        o.x = w0 * (o0.x + s0.x) + m * (o1.x + s1.x) + bo.x;
        o.y = w0 * (o0.y + s0.y) + m * (o1.y + s1.y) + bo.y;
        o.z = w0 * (o0.z + s0.z) + m * (o1.z + s1.z) + bo.z;
        o.w = w0 * (o0.w + s0.w) + m * (o1.w + s1.w) + bo.w;
        *(float4*)(out + (size_t)4 * i) = o;
    }
}

extern "C" void kernel_launch(void* const* d_in, const int* in_sizes, int n_in,
                              void* d_out, int out_size)
{
    const float* cur  = (const float*)d_in[0];
    const float* nobs = (const float*)d_in[1];
    const float* Wq   = (const float*)d_in[2];
    const float* bq   = (const float*)d_in[3];
    const float* Wc   = (const float*)d_in[4];
    const float* v    = (const float*)d_in[5];
    const float* Wout = (const float*)d_in[6];
    const float* bout = (const float*)d_in[7];
    const float* mix  = (const float*)d_in[8];
    float* out = (float*)d_out;

    cudaFuncSetAttribute(gemm_k, cudaFuncAttributeMaxDynamicSharedMemorySize, GSMEM);
    cudaFuncSetAttribute(score_ctx_kernel, cudaFuncAttributeMaxDynamicSharedMemorySize, SC_SMEM);

    // 0) round inputs to f16, transpose W
    prep_k<<<3072, 256>>>(cur, nobs, Wq, Wc, Wout);
    // 1) Both GEMMs (R10 champion): z=0 -> g_Pu, z=1 -> g_ZS
    gemm_k<<<dim3(8, 64, 2), 256, GSMEM>>>(bq);
    // 2) scores + softmax + align@Z -> g_O (R10 champion)
    score_ctx_kernel<<<256, 256, SC_SMEM>>>(v);
    // 3) mix + S + bias
    combine_kernel<<<1024, 256>>>(mix, bout, out);
}